// round 14
// baseline (speedup 1.0000x reference)
#include <cuda_runtime.h>
#include <math.h>

#define NPATHS 15
#define CG_TOTAL 615
#define MAXE 1000000
#define NPAD 53248            // 13 * 4096, >= N
#define TABN 16384            // gate table intervals over [0, 2]
#define NB_CG 15
#define NB_TAB 65             // covers TABN+1 = 16385 at 256/block
#define EPAD 1425984          // bound on padded slots (E + 8N), mult of 8
#define CAP 192               // shared-staging slots per chunk (mult of 8)

// path tables: (l1,l2,l3) enumerated as in the reference (l1 outer, l2 mid, l3 inner)
__device__ constexpr int PL1[NPATHS]  = {0,0,0,1,1,1,1,1,1,2,2,2,2,2,2};
__device__ constexpr int PL2[NPATHS]  = {0,1,2,0,1,1,1,2,2,0,1,1,2,2,2};
__device__ constexpr int PL3[NPATHS]  = {0,1,2,1,0,1,2,1,2,2,1,2,0,1,2};
__device__ constexpr int CGO[NPATHS]  = {0,1,10,35,44,53,80,125,170,245,270,315,390,415,490};
__device__ constexpr int GEOO[NPATHS] = {0,1,4,9,12,13,16,21,24,29,34,37,42,43,46};
__device__ constexpr int LOFF[3] = {0,1,4};

__device__ float g_cg[CG_TOTAL];
__device__ __align__(16) float g_Ai[NPAD * 8];
__device__ __align__(16) float g_tab[(TABN + 1) * 16];     // gate table (alpha*inv_avg baked)
__device__ __align__(16) float4 g_edata[EPAD];             // {sx,sy,sz, bitcast(src)} per slot
__device__ __align__(16) int g_dstS[EPAD];                 // dst per slot; -1 for pad slots
__device__ __align__(16) int g_count[NPAD];                // zero at entry; re-zeroed by scan
__device__ __align__(16) int g_off[NPAD + 4];              // 8-aligned starts
__device__ __align__(16) int g_cursor[NPAD];

// ---------------------------------------------------------------------------
// CG math helpers (double precision, replicates the reference)
// ---------------------------------------------------------------------------
__device__ double dfact(int n) {
    double r = 1.0;
    for (int i = 2; i <= n; ++i) r *= (double)i;
    return r;
}

__device__ double cgc(int j1, int j2, int j3, int m1, int m2, int m3) {
    if (m1 + m2 != m3) return 0.0;
    double pre = sqrt((double)(2 * j3 + 1) * dfact(j3 + j1 - j2) * dfact(j3 - j1 + j2) *
                      dfact(j1 + j2 - j3) / dfact(j1 + j2 + j3 + 1));
    pre *= sqrt(dfact(j3 + m3) * dfact(j3 - m3) * dfact(j1 - m1) * dfact(j1 + m1) *
                dfact(j2 - m2) * dfact(j2 + m2));
    double s = 0.0;
    for (int k = 0; k <= j1 + j2 - j3; ++k) {
        int d1 = j1 + j2 - j3 - k, d2 = j1 - m1 - k, d3 = j2 + m2 - k;
        int d4 = j3 - j2 + m1 + k, d5 = j3 - j1 - m2 + k;
        if (d1 < 0 || d2 < 0 || d3 < 0 || d4 < 0 || d5 < 0) continue;
        double t = 1.0 / (dfact(k) * dfact(d1) * dfact(d2) * dfact(d3) * dfact(d4) * dfact(d5));
        s += (k & 1) ? -t : t;
    }
    return pre * s;
}

__device__ void buildq(int l, double qr[5][5], double qi[5][5]) {
    for (int a = 0; a < 5; a++)
        for (int b = 0; b < 5; b++) { qr[a][b] = 0.0; qi[a][b] = 0.0; }
    const double isq = sqrt(0.5);
    for (int m = -l; m < 0; m++) {
        qr[l + m][l - m] = isq;
        qi[l + m][l + m] = -isq;
    }
    qr[l][l] = 1.0;
    for (int m = 1; m <= l; m++) {
        double sg = (m & 1) ? -1.0 : 1.0;
        qr[l + m][l + m] = sg * isq;
        qi[l + m][l - m] = sg * isq;
    }
    if (l == 1) {
        for (int a = 0; a < 5; a++)
            for (int b = 0; b < 5; b++) {
                double r = qr[a][b], i0 = qi[a][b];
                qr[a][b] = i0;
                qi[a][b] = -r;
            }
    } else if (l == 2) {
        for (int a = 0; a < 5; a++)
            for (int b = 0; b < 5; b++) { qr[a][b] = -qr[a][b]; qi[a][b] = -qi[a][b]; }
    }
}

// ---------------------------------------------------------------------------
// Mega init: CG init / gate table / node MLP / edge histogram / dstS = -1.
// ---------------------------------------------------------------------------
__global__ void __launch_bounds__(256) mega_init_kernel(
    const float* __restrict__ fw1, const float* __restrict__ fb1,
    const float* __restrict__ fw2, const float* __restrict__ fb2,
    const float* __restrict__ fw3, const float* __restrict__ fb3,
    float inv_avg,
    const float* __restrict__ emb_table, const int* __restrict__ A,
    const float* __restrict__ mw1, const float* __restrict__ mb1,
    const float* __restrict__ mw2, const float* __restrict__ mb2,
    const int* __restrict__ edst,
    int N, int E, int nbNode, int nbHist)
{
    __shared__ __align__(16) unsigned char sbuf[23040];
    int b = blockIdx.x;
    int tid = threadIdx.x;

    if (b < NB_CG) {
        double* q1r = (double*)(sbuf);
        double* q1i = q1r + 25;
        double* q2r = q1i + 25;
        double* q2i = q2r + 25;
        double* q3r = q2i + 25;
        double* q3i = q3r + 25;
        float* sAr = (float*)(q3i + 25);
        float* sAi = sAr + 128;
        int* sUseRe = (int*)(sAi + 128);

        int p = b;
        int l1 = PL1[p], l2 = PL2[p], l3 = PL3[p];
        int n1 = 2 * l1 + 1, n2 = 2 * l2 + 1, n3 = 2 * l3 + 1;
        int tot = n1 * n2 * n3;

        if (tid < 3) {
            double qr[5][5], qi[5][5];
            int l = (tid == 0) ? l1 : (tid == 1) ? l2 : l3;
            buildq(l, qr, qi);
            double* dr = (tid == 0) ? q1r : (tid == 1) ? q2r : q3r;
            double* di = (tid == 0) ? q1i : (tid == 1) ? q2i : q3i;
            for (int a = 0; a < 5; a++)
                for (int c = 0; c < 5; c++) { dr[a * 5 + c] = qr[a][c]; di[a * 5 + c] = qi[a][c]; }
        }
        __syncthreads();

        double ar = 0.0, ai = 0.0;
        if (tid < tot) {
            int i = tid / (n2 * n3);
            int rem = tid - i * (n2 * n3);
            int j = rem / n3;
            int k = rem - j * n3;
            for (int a = 0; a < n1; a++)
                for (int c = 0; c < n2; c++) {
                    double t12r = q1r[a * 5 + i] * q2r[c * 5 + j] - q1i[a * 5 + i] * q2i[c * 5 + j];
                    double t12i = q1r[a * 5 + i] * q2i[c * 5 + j] + q1i[a * 5 + i] * q2r[c * 5 + j];
                    if (t12r == 0.0 && t12i == 0.0) continue;
                    for (int cc = 0; cc < n3; cc++) {
                        double C = cgc(l1, l2, l3, a - l1, c - l2, cc - l3);
                        if (C == 0.0) continue;
                        double t3r = q3r[cc * 5 + k], t3i = -q3i[cc * 5 + k];
                        ar += (t12r * t3r - t12i * t3i) * C;
                        ai += (t12r * t3i + t12i * t3r) * C;
                    }
                }
        }
        if (tid < 128) {
            sAr[tid] = (tid < tot) ? (float)fabs(ar) : 0.0f;
            sAi[tid] = (tid < tot) ? (float)fabs(ai) : 0.0f;
        }
        __syncthreads();
        if (tid == 0) {
            float sr = 0.0f, si = 0.0f;
            for (int q = 0; q < tot; q++) { sr += sAr[q]; si += sAi[q]; }
            *sUseRe = (sr >= si) ? 1 : 0;
        }
        __syncthreads();
        if (tid < tot)
            g_cg[CGO[p] + tid] = (float)(*sUseRe ? ar : ai);
        return;
    }
    b -= NB_CG;

    if (b < NB_TAB) {
        float* F = (float*)sbuf;
        float* sW1 = F;
        float* sB1 = F + 512;
        float* sB2 = F + 576;
        float* sW2 = F + 640;
        float* sW3 = F + 4736;
        float* sB3 = F + 5696;

        for (int i = tid; i < 8 * 64; i += 256) sW1[i] = fw1[i];
        for (int i = tid; i < 64; i += 256) { sB1[i] = fb1[i]; sB2[i] = fb2[i]; }
        for (int i = tid; i < 64 * 64; i += 256) sW2[i] = fw2[i];
        for (int i = tid; i < 64 * NPATHS; i += 256) sW3[i] = fw3[i];
        for (int i = tid; i < NPATHS; i += 256) sB3[i] = fb3[i];
        __syncthreads();

        int idx = b * 256 + tid;
        if (idx > TABN) return;
        float len = (float)idx * (2.0f / (float)TABN);

        float emb[8];
        const float step = 2.0f / 9.0f;
        const float istep = 4.5f;
        const float cemb = 2.8284271247461903f / 1.12f;
#pragma unroll
        for (int i = 0; i < 8; i++) {
            float t = (len - (float)(i + 1) * step) * istep;
            emb[i] = __expf(-t * t) * cemb;
        }

        float h1[64];
#pragma unroll
        for (int j = 0; j < 64; j++) {
            float t = sB1[j];
#pragma unroll
            for (int i = 0; i < 8; i++) t += emb[i] * sW1[i * 64 + j];
            h1[j] = t / (1.0f + __expf(-t));
        }

        float gp[NPATHS];
#pragma unroll
        for (int p = 0; p < NPATHS; p++) gp[p] = sB3[p];
#pragma unroll 4
        for (int j = 0; j < 64; j++) {
            float t = sB2[j];
#pragma unroll
            for (int i = 0; i < 64; i++) t += h1[i] * sW2[i * 64 + j];
            float s = t / (1.0f + __expf(-t));
#pragma unroll
            for (int p = 0; p < NPATHS; p++) gp[p] += s * sW3[j * NPATHS + p];
        }

        const float ALP0 = 0.20412414523193154f;
        const float ALP1 = 0.14433756729740643f;
        float* row = g_tab + (size_t)idx * 16;
#pragma unroll
        for (int p = 0; p < NPATHS; p++) {
            float alpha = (PL3[p] == 0) ? ALP0 : ALP1;
            row[p] = gp[p] * alpha * inv_avg;
        }
        row[15] = 0.0f;
        return;
    }
    b -= NB_TAB;

    if (b < nbNode) {
        float* F = (float*)sbuf;
        float* sW1 = F;
        float* sB1 = F + 1024;
        float* sW2 = F + 1088;
        float* sB2 = F + 1600;
        float* sEmb = F + 1608;

        for (int i = tid; i < 16 * 64; i += 256) sW1[i] = mw1[i];
        for (int i = tid; i < 64; i += 256) sB1[i] = mb1[i];
        for (int i = tid; i < 64 * 8; i += 256) sW2[i] = mw2[i];
        for (int i = tid; i < 8; i += 256) sB2[i] = mb2[i];
        for (int i = tid; i < 10 * 16; i += 256) sEmb[i] = emb_table[i];
        __syncthreads();

        int n = b * 256 + tid;
        if (n >= N) return;
        int a = A[n];
        float x[16];
#pragma unroll
        for (int i = 0; i < 16; i++) x[i] = sEmb[a * 16 + i];
        float h[64];
#pragma unroll
        for (int j = 0; j < 64; j++) {
            float t = sB1[j];
#pragma unroll
            for (int i = 0; i < 16; i++) t += x[i] * sW1[i * 64 + j];
            h[j] = t / (1.0f + __expf(-t));
        }
#pragma unroll
        for (int o = 0; o < 8; o++) {
            float t = sB2[o];
#pragma unroll
            for (int j = 0; j < 64; j++) t += h[j] * sW2[j * 8 + o];
            g_Ai[n * 8 + o] = t;
        }
        return;
    }
    b -= nbNode;

    if (b < nbHist) {
        int e = b * 256 + tid;
        if (e < E) atomicAdd(&g_count[edst[e]], 1);
        return;
    }
    b -= nbHist;

    // ----- fill dstS with -1 (pad marker); scatter overwrites real slots -----
    int i = b * 256 + tid;
    if (i < EPAD / 4)
        ((int4*)g_dstS)[i] = make_int4(-1, -1, -1, -1);
}

// ---------------------------------------------------------------------------
// Coalesced exclusive scan over ALIGNED counts ((c+7)&~7); re-zeros g_count.
// ---------------------------------------------------------------------------
__global__ void __launch_bounds__(1024) scan_kernel() {
    __shared__ int warpsums[32];
    __shared__ int sCarry;
    int t = threadIdx.x;
    int lane = t & 31, wid = t >> 5;
    if (t == 0) sCarry = 0;
    __syncthreads();

#pragma unroll 1
    for (int base = 0; base < NPAD; base += 4096) {
        int4 v = *(const int4*)(g_count + base + t * 4);
        *(int4*)(g_count + base + t * 4) = make_int4(0, 0, 0, 0);
        int4 pv;
        pv.x = (v.x + 7) & ~7;
        pv.y = (v.y + 7) & ~7;
        pv.z = (v.z + 7) & ~7;
        pv.w = (v.w + 7) & ~7;
        int s = pv.x + pv.y + pv.z + pv.w;
        int ss = s;
#pragma unroll
        for (int d = 1; d < 32; d <<= 1) {
            int o = __shfl_up_sync(0xffffffffu, ss, d);
            if (lane >= d) ss += o;
        }
        if (lane == 31) warpsums[wid] = ss;
        __syncthreads();
        if (wid == 0) {
            int w = warpsums[lane];
#pragma unroll
            for (int d = 1; d < 32; d <<= 1) {
                int o = __shfl_up_sync(0xffffffffu, w, d);
                if (lane >= d) w += o;
            }
            warpsums[lane] = w;
        }
        __syncthreads();
        int carry = sCarry;
        int excl = carry + (wid ? warpsums[wid - 1] : 0) + (ss - s);
        int4 o;
        o.x = excl;
        o.y = excl + pv.x;
        o.z = o.y + pv.y;
        o.w = o.z + pv.z;
        *(int4*)(g_off + base + t * 4) = o;
        *(int4*)(g_cursor + base + t * 4) = o;
        int total = warpsums[31];
        __syncthreads();
        if (t == 0) sCarry = carry + total;
        __syncthreads();
    }
    if (t == 0) g_off[NPAD] = sCarry;
}

// ---------------------------------------------------------------------------
// Scatter: packed record + dst at padded cursor position.
// ---------------------------------------------------------------------------
__global__ void scatter_kernel(const int* __restrict__ esrc,
                               const int* __restrict__ edst,
                               const float* __restrict__ eshift, int E) {
    int e = blockIdx.x * blockDim.x + threadIdx.x;
    if (e >= E) return;
    int d = edst[e];
    int s = esrc[e];
    float sx = eshift[e * 3 + 0], sy = eshift[e * 3 + 1], sz = eshift[e * 3 + 2];
    int p = atomicAdd(&g_cursor[d], 1);
    g_edata[p] = make_float4(sx, sy, sz, __int_as_float(s));
    g_dstS[p] = d;
}

// ---------------------------------------------------------------------------
// Fused geo + accum + finalize: block = 8 nodes (contiguous slot range).
// Phase 1 per chunk: 256 threads compute geo+Ai into SHARED (float).
// Phase 2 per chunk: warp per node accumulates S from shared (float4 LDS).
// Epilogue: tpw transform, direct out[] stores.
// Dynamic smem layout (floats):
//   sGeo[52][CAP] | sAi[8][CAP] | sS[8][416] | sTP[1920] | sCG[615]
// ---------------------------------------------------------------------------
__global__ void __launch_bounds__(256) fused_kernel(
    const float* __restrict__ pos, const int* __restrict__ batch,
    const float* __restrict__ cell, const float* __restrict__ tpw,
    float* __restrict__ out, int N)
{
    extern __shared__ float sh[];
    float* sGeo = sh;                       // 52*CAP
    float* sAi  = sGeo + 52 * CAP;          // 8*CAP
    float* sS   = sAi + 8 * CAP;            // 8*416
    float* sTP  = sS + 8 * 416;             // 1920
    float* sCG  = sTP + 1920;               // 615

    int tid = threadIdx.x;
    for (int i = tid; i < NPATHS * 8 * 16; i += 256) sTP[i] = tpw[i];
    for (int i = tid; i < CG_TOTAL; i += 256) sCG[i] = g_cg[i];

    int node0 = blockIdx.x * 8;
    int lo = g_off[node0];
    int hi = g_off[node0 + 8];

    int warp = tid >> 5;
    int lane = tid & 31;
    int n = node0 + warp;
    int m = lane & 7;
    int q = lane >> 3;
    int base_pj = q * 13;                  // row 51 zeroed per chunk

    int nlo = 0, nhi = 0;
    if (n < N) { nlo = g_off[n]; nhi = g_off[n + 1]; }

    float acc[13];
#pragma unroll
    for (int r = 0; r < 13; r++) acc[r] = 0.0f;

    __syncthreads();

    for (int chunkLo = lo; chunkLo < hi; chunkLo += CAP) {
        int chunkHi = min(chunkLo + CAP, hi);
        int cnt = chunkHi - chunkLo;

        // ---- phase 1: geo into shared ----
        for (int local = tid; local < cnt; local += 256) {
            int slot = chunkLo + local;
            int d = g_dstS[slot];
            if (d < 0) {
#pragma unroll
                for (int mm = 0; mm < 8; mm++) sAi[mm * CAP + local] = 0.0f;
#pragma unroll
                for (int j = 0; j < 52; j++) sGeo[j * CAP + local] = 0.0f;
                continue;
            }
            float4 rec = g_edata[slot];
            int s = __float_as_int(rec.w);

            const float4* ap = (const float4*)(g_Ai + (size_t)s * 8);
            float4 a0 = ap[0], a1 = ap[1];
            sAi[0 * CAP + local] = a0.x;
            sAi[1 * CAP + local] = a0.y;
            sAi[2 * CAP + local] = a0.z;
            sAi[3 * CAP + local] = a0.w;
            sAi[4 * CAP + local] = a1.x;
            sAi[5 * CAP + local] = a1.y;
            sAi[6 * CAP + local] = a1.z;
            sAi[7 * CAP + local] = a1.w;

            int b = batch[s];
            const float* cl = cell + b * 9;
            float shx = rec.x * cl[0] + rec.y * cl[3] + rec.z * cl[6];
            float shy = rec.x * cl[1] + rec.y * cl[4] + rec.z * cl[7];
            float shz = rec.x * cl[2] + rec.y * cl[5] + rec.z * cl[8];
            float vx = pos[d * 3 + 0] - pos[s * 3 + 0] + shx;
            float vy = pos[d * 3 + 1] - pos[s * 3 + 1] + shy;
            float vz = pos[d * 3 + 2] - pos[s * 3 + 2] + shz;
            float L = sqrtf(vx * vx + vy * vy + vz * vz);
            float il = 1.0f / fmaxf(L, 1e-8f);
            float nx = vx * il, ny = vy * il, nz = vz * il;

            float Yv[9];
            const float s3 = 1.7320508075688772f;
            const float s15 = 3.872983346207417f;
            const float s5 = 2.23606797749979f;
            Yv[0] = 1.0f;
            Yv[1] = s3 * ny; Yv[2] = s3 * nz; Yv[3] = s3 * nx;
            Yv[4] = s15 * nx * ny;
            Yv[5] = s15 * ny * nz;
            Yv[6] = 0.5f * s5 * (3.0f * nz * nz - 1.0f);
            Yv[7] = s15 * nx * nz;
            Yv[8] = 0.5f * s15 * (nx * nx - ny * ny);

            float gp[16];
            {
                float t = L * ((float)TABN / 2.0f);
                int i0 = (int)t;
                i0 = min(i0, TABN - 1);
                float f = t - (float)i0;
                const float4* t0 = (const float4*)(g_tab + (size_t)i0 * 16);
                const float4* t1 = (const float4*)(g_tab + (size_t)(i0 + 1) * 16);
#pragma unroll
                for (int qq = 0; qq < 4; qq++) {
                    float4 a = t0[qq], c = t1[qq];
                    gp[qq * 4 + 0] = a.x + f * (c.x - a.x);
                    gp[qq * 4 + 1] = a.y + f * (c.y - a.y);
                    gp[qq * 4 + 2] = a.z + f * (c.z - a.z);
                    gp[qq * 4 + 3] = a.w + f * (c.w - a.w);
                }
            }

#pragma unroll
            for (int p = 0; p < NPATHS; p++) {
                const int l1 = PL1[p], l2 = PL2[p], l3 = PL3[p];
                const int o1 = LOFF[l1], o2 = LOFF[l2];
                const int n2d = 2 * l2 + 1, n3d = 2 * l3 + 1;
                float pacc[5];
#pragma unroll
                for (int k = 0; k < 5; k++) pacc[k] = 0.0f;
#pragma unroll
                for (int mm = 0; mm < 2 * l1 + 1; mm++) {
#pragma unroll
                    for (int nn = 0; nn < 2 * l2 + 1; nn++) {
                        float t = Yv[o1 + mm] * Yv[o2 + nn];
#pragma unroll
                        for (int k = 0; k < 2 * l3 + 1; k++)
                            pacc[k] += t * sCG[CGO[p] + (mm * n2d + nn) * n3d + k];
                    }
                }
#pragma unroll
                for (int k = 0; k < 2 * l3 + 1; k++)
                    sGeo[(size_t)(GEOO[p] + k) * CAP + local] = pacc[k] * gp[p];
            }
            sGeo[51 * CAP + local] = 0.0f;
        }
        __syncthreads();

        // ---- phase 2: accumulate from shared ----
        if (n < N) {
            int s0 = max(nlo, chunkLo);
            int s1 = min(nhi, chunkHi);
            for (int i = s0 - chunkLo; i < s1 - chunkLo; i += 4) {
                float4 a4 = *(const float4*)(sAi + m * CAP + i);
#pragma unroll
                for (int r = 0; r < 13; r++) {
                    float4 g4 = *(const float4*)(sGeo + (base_pj + r) * CAP + i);
                    acc[r] += a4.x * g4.x + a4.y * g4.y + a4.z * g4.z + a4.w * g4.w;
                }
            }
        }
        __syncthreads();
    }

    // ---- epilogue: write S to shared, transform, store out ----
    if (n < N) {
        float* srow = sS + warp * 416 + m * 52 + base_pj;
#pragma unroll
        for (int r = 0; r < 13; r++) srow[r] = acc[r];
    }
    __syncwarp();

    if (n >= N || lane >= 16) return;
    int c = lane;
    const float* S = sS + warp * 416;
    float* orow = out + (size_t)n * 144;

    const int P0[3] = {0, 4, 12};
    const int G0[3] = {0, 12, 42};
    const int P1[6] = {1, 3, 5, 7, 10, 13};
    const int G1[6] = {1, 9, 13, 21, 34, 43};
    const int P2[6] = {2, 6, 8, 9, 11, 14};
    const int G2[6] = {4, 16, 24, 29, 37, 46};

    {
        float a = 0.0f;
#pragma unroll
        for (int i = 0; i < 3; i++) {
            int p = P0[i], g = G0[i];
#pragma unroll
            for (int m2 = 0; m2 < 8; m2++)
                a += sTP[(p * 8 + m2) * 16 + c] * S[m2 * 52 + g];
        }
        orow[c] = a;
    }
#pragma unroll
    for (int k = 0; k < 3; k++) {
        float a = 0.0f;
#pragma unroll
        for (int i = 0; i < 6; i++) {
            int p = P1[i], g = G1[i] + k;
#pragma unroll
            for (int m2 = 0; m2 < 8; m2++)
                a += sTP[(p * 8 + m2) * 16 + c] * S[m2 * 52 + g];
        }
        orow[16 + 3 * c + k] = a;
    }
#pragma unroll
    for (int k = 0; k < 5; k++) {
        float a = 0.0f;
#pragma unroll
        for (int i = 0; i < 6; i++) {
            int p = P2[i], g = G2[i] + k;
#pragma unroll
            for (int m2 = 0; m2 < 8; m2++)
                a += sTP[(p * 8 + m2) * 16 + c] * S[m2 * 52 + g];
        }
        orow[64 + 5 * c + k] = a;
    }
}

// ---------------------------------------------------------------------------
extern "C" void kernel_launch(void* const* d_in, const int* in_sizes, int n_in,
                              void* d_out, int out_size)
{
    const float* pos    = (const float*)d_in[0];
    const int*   A      = (const int*)d_in[1];
    const int*   batch  = (const int*)d_in[2];
    const int*   esrc   = (const int*)d_in[3];
    const int*   edst   = (const int*)d_in[4];
    const float* eshift = (const float*)d_in[5];
    const float* cell   = (const float*)d_in[6];
    const float* embt   = (const float*)d_in[7];
    const float* mw1    = (const float*)d_in[8];
    const float* mb1    = (const float*)d_in[9];
    const float* mw2    = (const float*)d_in[10];
    const float* mb2    = (const float*)d_in[11];
    const float* fw1    = (const float*)d_in[12];
    const float* fb1    = (const float*)d_in[13];
    const float* fw2    = (const float*)d_in[14];
    const float* fb2    = (const float*)d_in[15];
    const float* fw3    = (const float*)d_in[16];
    const float* fb3    = (const float*)d_in[17];
    const float* tpw    = (const float*)d_in[18];
    float* out = (float*)d_out;

    int N = in_sizes[1];
    int E = in_sizes[3];
    float avg = (float)E / (float)N;
    float inv_avg = 1.0f / fmaxf(avg, 1e-8f);

    int nbNode = (N + 255) / 256;
    int nbHist = (E + 255) / 256;
    int nbFill = (EPAD / 4 + 255) / 256;
    int megaBlocks = NB_CG + NB_TAB + nbNode + nbHist + nbFill;

    // dynamic smem for fused kernel
    int smemBytes = (52 * CAP + 8 * CAP + 8 * 416 + 1920 + CG_TOTAL) * 4;
    static int attrSet = 0;
    if (!attrSet) {
        cudaFuncSetAttribute(fused_kernel, cudaFuncAttributeMaxDynamicSharedMemorySize, smemBytes);
        attrSet = 1;
    }

    mega_init_kernel<<<megaBlocks, 256>>>(fw1, fb1, fw2, fb2, fw3, fb3, inv_avg,
                                          embt, A, mw1, mb1, mw2, mb2, edst,
                                          N, E, nbNode, nbHist);
    scan_kernel<<<1, 1024>>>();
    scatter_kernel<<<(E + 255) / 256, 256>>>(esrc, edst, eshift, E);
    fused_kernel<<<(N + 7) / 8, 256, smemBytes>>>(pos, batch, cell, tpw, out, N);
}

// round 15
// speedup vs baseline: 1.1209x; 1.1209x over previous
#include <cuda_runtime.h>
#include <math.h>

#define NPATHS 15
#define CG_TOTAL 615
#define MAXE 1000000
#define NPAD 53248            // 13 * 4096, >= N
#define TABN 16384            // gate table intervals over [0, 2]
#define NB_CG 15
#define NB_TAB 65             // covers TABN+1 = 16385 at 256/block
#define EPAD 1425984          // bound on padded slots (E + 8N), mult of 8
#define CAP 192               // shared-staging slots per chunk (mult of 8)
#define CAPP 196              // smem row pitch (== 4 mod 32 banks, mult of 4)

// path tables: (l1,l2,l3) enumerated as in the reference (l1 outer, l2 mid, l3 inner)
__device__ constexpr int PL1[NPATHS]  = {0,0,0,1,1,1,1,1,1,2,2,2,2,2,2};
__device__ constexpr int PL2[NPATHS]  = {0,1,2,0,1,1,1,2,2,0,1,1,2,2,2};
__device__ constexpr int PL3[NPATHS]  = {0,1,2,1,0,1,2,1,2,2,1,2,0,1,2};
__device__ constexpr int CGO[NPATHS]  = {0,1,10,35,44,53,80,125,170,245,270,315,390,415,490};
__device__ constexpr int GEOO[NPATHS] = {0,1,4,9,12,13,16,21,24,29,34,37,42,43,46};
__device__ constexpr int LOFF[3] = {0,1,4};

__device__ float g_cg[CG_TOTAL];
__device__ __align__(16) float g_Ai[NPAD * 8];
__device__ __align__(16) float g_tab[(TABN + 1) * 16];     // gate table (alpha*inv_avg baked)
__device__ __align__(16) float4 g_edata[EPAD];             // {sx,sy,sz, bitcast(src)} per slot
__device__ __align__(16) int g_dstS[EPAD];                 // dst per slot; -1 for pad slots
__device__ __align__(16) int g_count[NPAD];                // zero at entry; re-zeroed by scan
__device__ __align__(16) int g_off[NPAD + 4];              // 8-aligned starts
__device__ __align__(16) int g_cursor[NPAD];

// ---------------------------------------------------------------------------
// CG math helpers (double precision, replicates the reference)
// ---------------------------------------------------------------------------
__device__ double dfact(int n) {
    double r = 1.0;
    for (int i = 2; i <= n; ++i) r *= (double)i;
    return r;
}

__device__ double cgc(int j1, int j2, int j3, int m1, int m2, int m3) {
    if (m1 + m2 != m3) return 0.0;
    double pre = sqrt((double)(2 * j3 + 1) * dfact(j3 + j1 - j2) * dfact(j3 - j1 + j2) *
                      dfact(j1 + j2 - j3) / dfact(j1 + j2 + j3 + 1));
    pre *= sqrt(dfact(j3 + m3) * dfact(j3 - m3) * dfact(j1 - m1) * dfact(j1 + m1) *
                dfact(j2 - m2) * dfact(j2 + m2));
    double s = 0.0;
    for (int k = 0; k <= j1 + j2 - j3; ++k) {
        int d1 = j1 + j2 - j3 - k, d2 = j1 - m1 - k, d3 = j2 + m2 - k;
        int d4 = j3 - j2 + m1 + k, d5 = j3 - j1 - m2 + k;
        if (d1 < 0 || d2 < 0 || d3 < 0 || d4 < 0 || d5 < 0) continue;
        double t = 1.0 / (dfact(k) * dfact(d1) * dfact(d2) * dfact(d3) * dfact(d4) * dfact(d5));
        s += (k & 1) ? -t : t;
    }
    return pre * s;
}

__device__ void buildq(int l, double qr[5][5], double qi[5][5]) {
    for (int a = 0; a < 5; a++)
        for (int b = 0; b < 5; b++) { qr[a][b] = 0.0; qi[a][b] = 0.0; }
    const double isq = sqrt(0.5);
    for (int m = -l; m < 0; m++) {
        qr[l + m][l - m] = isq;
        qi[l + m][l + m] = -isq;
    }
    qr[l][l] = 1.0;
    for (int m = 1; m <= l; m++) {
        double sg = (m & 1) ? -1.0 : 1.0;
        qr[l + m][l + m] = sg * isq;
        qi[l + m][l - m] = sg * isq;
    }
    if (l == 1) {
        for (int a = 0; a < 5; a++)
            for (int b = 0; b < 5; b++) {
                double r = qr[a][b], i0 = qi[a][b];
                qr[a][b] = i0;
                qi[a][b] = -r;
            }
    } else if (l == 2) {
        for (int a = 0; a < 5; a++)
            for (int b = 0; b < 5; b++) { qr[a][b] = -qr[a][b]; qi[a][b] = -qi[a][b]; }
    }
}

// ---------------------------------------------------------------------------
// Mega init: CG init / gate table / node MLP / edge histogram / dstS = -1.
// ---------------------------------------------------------------------------
__global__ void __launch_bounds__(256) mega_init_kernel(
    const float* __restrict__ fw1, const float* __restrict__ fb1,
    const float* __restrict__ fw2, const float* __restrict__ fb2,
    const float* __restrict__ fw3, const float* __restrict__ fb3,
    float inv_avg,
    const float* __restrict__ emb_table, const int* __restrict__ A,
    const float* __restrict__ mw1, const float* __restrict__ mb1,
    const float* __restrict__ mw2, const float* __restrict__ mb2,
    const int* __restrict__ edst,
    int N, int E, int nbNode, int nbHist)
{
    __shared__ __align__(16) unsigned char sbuf[23040];
    int b = blockIdx.x;
    int tid = threadIdx.x;

    if (b < NB_CG) {
        double* q1r = (double*)(sbuf);
        double* q1i = q1r + 25;
        double* q2r = q1i + 25;
        double* q2i = q2r + 25;
        double* q3r = q2i + 25;
        double* q3i = q3r + 25;
        float* sAr = (float*)(q3i + 25);
        float* sAi = sAr + 128;
        int* sUseRe = (int*)(sAi + 128);

        int p = b;
        int l1 = PL1[p], l2 = PL2[p], l3 = PL3[p];
        int n1 = 2 * l1 + 1, n2 = 2 * l2 + 1, n3 = 2 * l3 + 1;
        int tot = n1 * n2 * n3;

        if (tid < 3) {
            double qr[5][5], qi[5][5];
            int l = (tid == 0) ? l1 : (tid == 1) ? l2 : l3;
            buildq(l, qr, qi);
            double* dr = (tid == 0) ? q1r : (tid == 1) ? q2r : q3r;
            double* di = (tid == 0) ? q1i : (tid == 1) ? q2i : q3i;
            for (int a = 0; a < 5; a++)
                for (int c = 0; c < 5; c++) { dr[a * 5 + c] = qr[a][c]; di[a * 5 + c] = qi[a][c]; }
        }
        __syncthreads();

        double ar = 0.0, ai = 0.0;
        if (tid < tot) {
            int i = tid / (n2 * n3);
            int rem = tid - i * (n2 * n3);
            int j = rem / n3;
            int k = rem - j * n3;
            for (int a = 0; a < n1; a++)
                for (int c = 0; c < n2; c++) {
                    double t12r = q1r[a * 5 + i] * q2r[c * 5 + j] - q1i[a * 5 + i] * q2i[c * 5 + j];
                    double t12i = q1r[a * 5 + i] * q2i[c * 5 + j] + q1i[a * 5 + i] * q2r[c * 5 + j];
                    if (t12r == 0.0 && t12i == 0.0) continue;
                    for (int cc = 0; cc < n3; cc++) {
                        double C = cgc(l1, l2, l3, a - l1, c - l2, cc - l3);
                        if (C == 0.0) continue;
                        double t3r = q3r[cc * 5 + k], t3i = -q3i[cc * 5 + k];
                        ar += (t12r * t3r - t12i * t3i) * C;
                        ai += (t12r * t3i + t12i * t3r) * C;
                    }
                }
        }
        if (tid < 128) {
            sAr[tid] = (tid < tot) ? (float)fabs(ar) : 0.0f;
            sAi[tid] = (tid < tot) ? (float)fabs(ai) : 0.0f;
        }
        __syncthreads();
        if (tid == 0) {
            float sr = 0.0f, si = 0.0f;
            for (int q = 0; q < tot; q++) { sr += sAr[q]; si += sAi[q]; }
            *sUseRe = (sr >= si) ? 1 : 0;
        }
        __syncthreads();
        if (tid < tot)
            g_cg[CGO[p] + tid] = (float)(*sUseRe ? ar : ai);
        return;
    }
    b -= NB_CG;

    if (b < NB_TAB) {
        float* F = (float*)sbuf;
        float* sW1 = F;
        float* sB1 = F + 512;
        float* sB2 = F + 576;
        float* sW2 = F + 640;
        float* sW3 = F + 4736;
        float* sB3 = F + 5696;

        for (int i = tid; i < 8 * 64; i += 256) sW1[i] = fw1[i];
        for (int i = tid; i < 64; i += 256) { sB1[i] = fb1[i]; sB2[i] = fb2[i]; }
        for (int i = tid; i < 64 * 64; i += 256) sW2[i] = fw2[i];
        for (int i = tid; i < 64 * NPATHS; i += 256) sW3[i] = fw3[i];
        for (int i = tid; i < NPATHS; i += 256) sB3[i] = fb3[i];
        __syncthreads();

        int idx = b * 256 + tid;
        if (idx > TABN) return;
        float len = (float)idx * (2.0f / (float)TABN);

        float emb[8];
        const float step = 2.0f / 9.0f;
        const float istep = 4.5f;
        const float cemb = 2.8284271247461903f / 1.12f;
#pragma unroll
        for (int i = 0; i < 8; i++) {
            float t = (len - (float)(i + 1) * step) * istep;
            emb[i] = __expf(-t * t) * cemb;
        }

        float h1[64];
#pragma unroll
        for (int j = 0; j < 64; j++) {
            float t = sB1[j];
#pragma unroll
            for (int i = 0; i < 8; i++) t += emb[i] * sW1[i * 64 + j];
            h1[j] = t / (1.0f + __expf(-t));
        }

        float gp[NPATHS];
#pragma unroll
        for (int p = 0; p < NPATHS; p++) gp[p] = sB3[p];
#pragma unroll 4
        for (int j = 0; j < 64; j++) {
            float t = sB2[j];
#pragma unroll
            for (int i = 0; i < 64; i++) t += h1[i] * sW2[i * 64 + j];
            float s = t / (1.0f + __expf(-t));
#pragma unroll
            for (int p = 0; p < NPATHS; p++) gp[p] += s * sW3[j * NPATHS + p];
        }

        const float ALP0 = 0.20412414523193154f;
        const float ALP1 = 0.14433756729740643f;
        float* row = g_tab + (size_t)idx * 16;
#pragma unroll
        for (int p = 0; p < NPATHS; p++) {
            float alpha = (PL3[p] == 0) ? ALP0 : ALP1;
            row[p] = gp[p] * alpha * inv_avg;
        }
        row[15] = 0.0f;
        return;
    }
    b -= NB_TAB;

    if (b < nbNode) {
        float* F = (float*)sbuf;
        float* sW1 = F;
        float* sB1 = F + 1024;
        float* sW2 = F + 1088;
        float* sB2 = F + 1600;
        float* sEmb = F + 1608;

        for (int i = tid; i < 16 * 64; i += 256) sW1[i] = mw1[i];
        for (int i = tid; i < 64; i += 256) sB1[i] = mb1[i];
        for (int i = tid; i < 64 * 8; i += 256) sW2[i] = mw2[i];
        for (int i = tid; i < 8; i += 256) sB2[i] = mb2[i];
        for (int i = tid; i < 10 * 16; i += 256) sEmb[i] = emb_table[i];
        __syncthreads();

        int n = b * 256 + tid;
        if (n >= N) return;
        int a = A[n];
        float x[16];
#pragma unroll
        for (int i = 0; i < 16; i++) x[i] = sEmb[a * 16 + i];
        float h[64];
#pragma unroll
        for (int j = 0; j < 64; j++) {
            float t = sB1[j];
#pragma unroll
            for (int i = 0; i < 16; i++) t += x[i] * sW1[i * 64 + j];
            h[j] = t / (1.0f + __expf(-t));
        }
#pragma unroll
        for (int o = 0; o < 8; o++) {
            float t = sB2[o];
#pragma unroll
            for (int j = 0; j < 64; j++) t += h[j] * sW2[j * 8 + o];
            g_Ai[n * 8 + o] = t;
        }
        return;
    }
    b -= nbNode;

    if (b < nbHist) {
        int e = b * 256 + tid;
        if (e < E) atomicAdd(&g_count[edst[e]], 1);
        return;
    }
    b -= nbHist;

    // ----- fill dstS with -1 (pad marker); scatter overwrites real slots -----
    int i = b * 256 + tid;
    if (i < EPAD / 4)
        ((int4*)g_dstS)[i] = make_int4(-1, -1, -1, -1);
}

// ---------------------------------------------------------------------------
// Coalesced exclusive scan over ALIGNED counts ((c+7)&~7); re-zeros g_count.
// ---------------------------------------------------------------------------
__global__ void __launch_bounds__(1024) scan_kernel() {
    __shared__ int warpsums[32];
    __shared__ int sCarry;
    int t = threadIdx.x;
    int lane = t & 31, wid = t >> 5;
    if (t == 0) sCarry = 0;
    __syncthreads();

#pragma unroll 1
    for (int base = 0; base < NPAD; base += 4096) {
        int4 v = *(const int4*)(g_count + base + t * 4);
        *(int4*)(g_count + base + t * 4) = make_int4(0, 0, 0, 0);
        int4 pv;
        pv.x = (v.x + 7) & ~7;
        pv.y = (v.y + 7) & ~7;
        pv.z = (v.z + 7) & ~7;
        pv.w = (v.w + 7) & ~7;
        int s = pv.x + pv.y + pv.z + pv.w;
        int ss = s;
#pragma unroll
        for (int d = 1; d < 32; d <<= 1) {
            int o = __shfl_up_sync(0xffffffffu, ss, d);
            if (lane >= d) ss += o;
        }
        if (lane == 31) warpsums[wid] = ss;
        __syncthreads();
        if (wid == 0) {
            int w = warpsums[lane];
#pragma unroll
            for (int d = 1; d < 32; d <<= 1) {
                int o = __shfl_up_sync(0xffffffffu, w, d);
                if (lane >= d) w += o;
            }
            warpsums[lane] = w;
        }
        __syncthreads();
        int carry = sCarry;
        int excl = carry + (wid ? warpsums[wid - 1] : 0) + (ss - s);
        int4 o;
        o.x = excl;
        o.y = excl + pv.x;
        o.z = o.y + pv.y;
        o.w = o.z + pv.z;
        *(int4*)(g_off + base + t * 4) = o;
        *(int4*)(g_cursor + base + t * 4) = o;
        int total = warpsums[31];
        __syncthreads();
        if (t == 0) sCarry = carry + total;
        __syncthreads();
    }
    if (t == 0) g_off[NPAD] = sCarry;
}

// ---------------------------------------------------------------------------
// Scatter: packed record + dst at padded cursor position.
// ---------------------------------------------------------------------------
__global__ void scatter_kernel(const int* __restrict__ esrc,
                               const int* __restrict__ edst,
                               const float* __restrict__ eshift, int E) {
    int e = blockIdx.x * blockDim.x + threadIdx.x;
    if (e >= E) return;
    int d = edst[e];
    int s = esrc[e];
    float sx = eshift[e * 3 + 0], sy = eshift[e * 3 + 1], sz = eshift[e * 3 + 2];
    int p = atomicAdd(&g_cursor[d], 1);
    g_edata[p] = make_float4(sx, sy, sz, __int_as_float(s));
    g_dstS[p] = d;
}

// ---------------------------------------------------------------------------
// Fused geo + accum + finalize: block = 8 nodes (contiguous slot range).
// Smem (floats): sGeo[52][CAPP] | sAi[8][CAPP] | sCG[615]
// Epilogue overlays sS[8*416] and sTP[1920] onto the sGeo region.
// CAPP = 196 (== 4 mod 32) -> conflict-free row strides.
// ---------------------------------------------------------------------------
__global__ void __launch_bounds__(256, 2) fused_kernel(
    const float* __restrict__ pos, const int* __restrict__ batch,
    const float* __restrict__ cell, const float* __restrict__ tpw,
    float* __restrict__ out, int N)
{
    extern __shared__ float sh[];
    float* sGeo = sh;                       // 52*CAPP
    float* sAi  = sGeo + 52 * CAPP;         // 8*CAPP
    float* sCG  = sAi + 8 * CAPP;           // 615
    // epilogue overlays (valid after final loop sync):
    float* sS   = sh;                       // 8*416 = 3328
    float* sTP  = sh + 3328;                // 1920  (ends 5248 < 52*CAPP)

    int tid = threadIdx.x;
    for (int i = tid; i < CG_TOTAL; i += 256) sCG[i] = g_cg[i];

    int node0 = blockIdx.x * 8;
    int lo = g_off[node0];
    int hi = g_off[node0 + 8];

    int warp = tid >> 5;
    int lane = tid & 31;
    int n = node0 + warp;
    int m = lane & 7;
    int q = lane >> 3;
    int base_pj = q * 13;                  // row 51 zeroed per chunk

    int nlo = 0, nhi = 0;
    if (n < N) { nlo = g_off[n]; nhi = g_off[n + 1]; }

    float acc[13];
#pragma unroll
    for (int r = 0; r < 13; r++) acc[r] = 0.0f;

    __syncthreads();

    for (int chunkLo = lo; chunkLo < hi; chunkLo += CAP) {
        int chunkHi = min(chunkLo + CAP, hi);
        int cnt = chunkHi - chunkLo;

        // ---- phase 1: geo into shared ----
        for (int local = tid; local < cnt; local += 256) {
            int slot = chunkLo + local;
            int d = g_dstS[slot];
            if (d < 0) {
#pragma unroll
                for (int mm = 0; mm < 8; mm++) sAi[mm * CAPP + local] = 0.0f;
#pragma unroll
                for (int j = 0; j < 52; j++) sGeo[j * CAPP + local] = 0.0f;
                continue;
            }
            float4 rec = g_edata[slot];
            int s = __float_as_int(rec.w);

            const float4* ap = (const float4*)(g_Ai + (size_t)s * 8);
            float4 a0 = ap[0], a1 = ap[1];
            sAi[0 * CAPP + local] = a0.x;
            sAi[1 * CAPP + local] = a0.y;
            sAi[2 * CAPP + local] = a0.z;
            sAi[3 * CAPP + local] = a0.w;
            sAi[4 * CAPP + local] = a1.x;
            sAi[5 * CAPP + local] = a1.y;
            sAi[6 * CAPP + local] = a1.z;
            sAi[7 * CAPP + local] = a1.w;

            int b = batch[s];
            const float* cl = cell + b * 9;
            float shx = rec.x * cl[0] + rec.y * cl[3] + rec.z * cl[6];
            float shy = rec.x * cl[1] + rec.y * cl[4] + rec.z * cl[7];
            float shz = rec.x * cl[2] + rec.y * cl[5] + rec.z * cl[8];
            float vx = pos[d * 3 + 0] - pos[s * 3 + 0] + shx;
            float vy = pos[d * 3 + 1] - pos[s * 3 + 1] + shy;
            float vz = pos[d * 3 + 2] - pos[s * 3 + 2] + shz;
            float L = sqrtf(vx * vx + vy * vy + vz * vz);
            float il = 1.0f / fmaxf(L, 1e-8f);
            float nx = vx * il, ny = vy * il, nz = vz * il;

            float Yv[9];
            const float s3 = 1.7320508075688772f;
            const float s15 = 3.872983346207417f;
            const float s5 = 2.23606797749979f;
            Yv[0] = 1.0f;
            Yv[1] = s3 * ny; Yv[2] = s3 * nz; Yv[3] = s3 * nx;
            Yv[4] = s15 * nx * ny;
            Yv[5] = s15 * ny * nz;
            Yv[6] = 0.5f * s5 * (3.0f * nz * nz - 1.0f);
            Yv[7] = s15 * nx * nz;
            Yv[8] = 0.5f * s15 * (nx * nx - ny * ny);

            float gp[16];
            {
                float t = L * ((float)TABN / 2.0f);
                int i0 = (int)t;
                i0 = min(i0, TABN - 1);
                float f = t - (float)i0;
                const float4* t0 = (const float4*)(g_tab + (size_t)i0 * 16);
                const float4* t1 = (const float4*)(g_tab + (size_t)(i0 + 1) * 16);
#pragma unroll
                for (int qq = 0; qq < 4; qq++) {
                    float4 a = t0[qq], c = t1[qq];
                    gp[qq * 4 + 0] = a.x + f * (c.x - a.x);
                    gp[qq * 4 + 1] = a.y + f * (c.y - a.y);
                    gp[qq * 4 + 2] = a.z + f * (c.z - a.z);
                    gp[qq * 4 + 3] = a.w + f * (c.w - a.w);
                }
            }

#pragma unroll
            for (int p = 0; p < NPATHS; p++) {
                const int l1 = PL1[p], l2 = PL2[p], l3 = PL3[p];
                const int o1 = LOFF[l1], o2 = LOFF[l2];
                const int n2d = 2 * l2 + 1, n3d = 2 * l3 + 1;
                float pacc[5];
#pragma unroll
                for (int k = 0; k < 5; k++) pacc[k] = 0.0f;
#pragma unroll
                for (int mm = 0; mm < 2 * l1 + 1; mm++) {
#pragma unroll
                    for (int nn = 0; nn < 2 * l2 + 1; nn++) {
                        float t = Yv[o1 + mm] * Yv[o2 + nn];
#pragma unroll
                        for (int k = 0; k < 2 * l3 + 1; k++)
                            pacc[k] += t * sCG[CGO[p] + (mm * n2d + nn) * n3d + k];
                    }
                }
#pragma unroll
                for (int k = 0; k < 2 * l3 + 1; k++)
                    sGeo[(GEOO[p] + k) * CAPP + local] = pacc[k] * gp[p];
            }
            sGeo[51 * CAPP + local] = 0.0f;
        }
        __syncthreads();

        // ---- phase 2: accumulate from shared ----
        if (n < N) {
            int s0 = max(nlo, chunkLo);
            int s1 = min(nhi, chunkHi);
            for (int i = s0 - chunkLo; i < s1 - chunkLo; i += 4) {
                float4 a4 = *(const float4*)(sAi + m * CAPP + i);
#pragma unroll
                for (int r = 0; r < 13; r++) {
                    float4 g4 = *(const float4*)(sGeo + (base_pj + r) * CAPP + i);
                    acc[r] += a4.x * g4.x + a4.y * g4.y + a4.z * g4.z + a4.w * g4.w;
                }
            }
        }
        __syncthreads();
    }

    // ---- epilogue: overlay sS/sTP onto sGeo region ----
    for (int i = tid; i < NPATHS * 8 * 16; i += 256) sTP[i] = tpw[i];
    if (n < N) {
        float* srow = sS + warp * 416 + m * 52 + base_pj;
#pragma unroll
        for (int r = 0; r < 13; r++) srow[r] = acc[r];
    }
    __syncthreads();

    if (n >= N || lane >= 16) return;
    int c = lane;
    const float* S = sS + warp * 416;
    float* orow = out + (size_t)n * 144;

    const int P0[3] = {0, 4, 12};
    const int G0[3] = {0, 12, 42};
    const int P1[6] = {1, 3, 5, 7, 10, 13};
    const int G1[6] = {1, 9, 13, 21, 34, 43};
    const int P2[6] = {2, 6, 8, 9, 11, 14};
    const int G2[6] = {4, 16, 24, 29, 37, 46};

    {
        float a = 0.0f;
#pragma unroll
        for (int i = 0; i < 3; i++) {
            int p = P0[i], g = G0[i];
#pragma unroll
            for (int m2 = 0; m2 < 8; m2++)
                a += sTP[(p * 8 + m2) * 16 + c] * S[m2 * 52 + g];
        }
        orow[c] = a;
    }
#pragma unroll
    for (int k = 0; k < 3; k++) {
        float a = 0.0f;
#pragma unroll
        for (int i = 0; i < 6; i++) {
            int p = P1[i], g = G1[i] + k;
#pragma unroll
            for (int m2 = 0; m2 < 8; m2++)
                a += sTP[(p * 8 + m2) * 16 + c] * S[m2 * 52 + g];
        }
        orow[16 + 3 * c + k] = a;
    }
#pragma unroll
    for (int k = 0; k < 5; k++) {
        float a = 0.0f;
#pragma unroll
        for (int i = 0; i < 6; i++) {
            int p = P2[i], g = G2[i] + k;
#pragma unroll
            for (int m2 = 0; m2 < 8; m2++)
                a += sTP[(p * 8 + m2) * 16 + c] * S[m2 * 52 + g];
        }
        orow[64 + 5 * c + k] = a;
    }
}

// ---------------------------------------------------------------------------
extern "C" void kernel_launch(void* const* d_in, const int* in_sizes, int n_in,
                              void* d_out, int out_size)
{
    const float* pos    = (const float*)d_in[0];
    const int*   A      = (const int*)d_in[1];
    const int*   batch  = (const int*)d_in[2];
    const int*   esrc   = (const int*)d_in[3];
    const int*   edst   = (const int*)d_in[4];
    const float* eshift = (const float*)d_in[5];
    const float* cell   = (const float*)d_in[6];
    const float* embt   = (const float*)d_in[7];
    const float* mw1    = (const float*)d_in[8];
    const float* mb1    = (const float*)d_in[9];
    const float* mw2    = (const float*)d_in[10];
    const float* mb2    = (const float*)d_in[11];
    const float* fw1    = (const float*)d_in[12];
    const float* fb1    = (const float*)d_in[13];
    const float* fw2    = (const float*)d_in[14];
    const float* fb2    = (const float*)d_in[15];
    const float* fw3    = (const float*)d_in[16];
    const float* fb3    = (const float*)d_in[17];
    const float* tpw    = (const float*)d_in[18];
    float* out = (float*)d_out;

    int N = in_sizes[1];
    int E = in_sizes[3];
    float avg = (float)E / (float)N;
    float inv_avg = 1.0f / fmaxf(avg, 1e-8f);

    int nbNode = (N + 255) / 256;
    int nbHist = (E + 255) / 256;
    int nbFill = (EPAD / 4 + 255) / 256;
    int megaBlocks = NB_CG + NB_TAB + nbNode + nbHist + nbFill;

    int smemBytes = (60 * CAPP + CG_TOTAL) * 4;   // 49500 B
    static int attrSet = 0;
    if (!attrSet) {
        cudaFuncSetAttribute(fused_kernel, cudaFuncAttributeMaxDynamicSharedMemorySize, smemBytes);
        attrSet = 1;
    }

    mega_init_kernel<<<megaBlocks, 256>>>(fw1, fb1, fw2, fb2, fw3, fb3, inv_avg,
                                          embt, A, mw1, mb1, mw2, mb2, edst,
                                          N, E, nbNode, nbHist);
    scan_kernel<<<1, 1024>>>();
    scatter_kernel<<<(E + 255) / 256, 256>>>(esrc, edst, eshift, E);
    fused_kernel<<<(N + 7) / 8, 256, smemBytes>>>(pos, batch, cell, tpw, out, N);
}